// round 15
// baseline (speedup 1.0000x reference)
#include <cuda_runtime.h>
#include <cuda_fp16.h>

// Problem constants (static per reference)
constexpr int B  = 2;
constexpr int S  = 6;
constexpr int N  = 10000;
constexpr int C  = 128;
constexpr int D  = 4;
constexpr int NH = 4;     // heads
constexpr int NP = 8;     // points
constexpr int Hf = 32;
constexpr int Wf = 88;
constexpr int M  = Hf * Wf;        // 2816
constexpr int WP = Wf + 4;         // 92  (2-px pad each side)
constexpr int HP = Hf + 4;         // 36
constexpr int MP = HP * WP;        // 3312 padded pixels
constexpr int RING = MP - M;       // 496 pad cells per (s,b)
constexpr int MASK_ELEMS = S * B * N * D;  // 480000
constexpr int NROWS = B * N;               // 20000
constexpr int PBLOCKS = 64;                // fused prep blocks
constexpr int VBLOCKS = (S * B * M) / 64;  // 528 vproj tiles
constexpr int QBLOCKS = (NROWS + 63) / 64; // 313 qproj tiles
constexpr int OBLOCKS = (NROWS + 31) / 32; // 625 out tiles

// Scratch (device globals; no allocation allowed)
__device__ __half   g_vproj [S * B * MP * C];       // padded (s,b,py,px,c) fp16
__device__ float    g_off   [B * N * NH * NP * 2];  // offsets (pixel units)
__device__ float    g_logits[B * N * NH * NP];      // attn logits
__device__ float    g_slots [B * N * C];            // masked-mean slots
__device__ unsigned g_mask_occ;                     // byte-position occupancy

// packed fp32x2 FMA (Blackwell): d = a*b + d elementwise
__device__ __forceinline__ void ffma2(float2& d, float2 a, float2 b) {
    asm("fma.rn.f32x2 %0, %1, %2, %0;"
        : "+l"(reinterpret_cast<unsigned long long&>(d))
        : "l"(reinterpret_cast<unsigned long long&>(a)),
          "l"(reinterpret_cast<unsigned long long&>(b)));
}

__device__ __forceinline__ int mask_nz(const unsigned char* __restrict__ mask,
                                       long long elem, int st)
{
    const unsigned char* p = mask + elem * st;
    int v = 0;
    for (int j = 0; j < st; j++) v |= p[j];
    return v != 0;
}

// ---------------------------------------------------------------------------
// prep body: pad-ring zerofill + mask dtype probe (fused into k_proj grid).
// Writes only the ring (disjoint from vproj interior) and g_mask_occ
// (consumed by k_sample, which launches after k_proj completes).
// ---------------------------------------------------------------------------
__device__ void prep_body(int bid, const uint4* __restrict__ mask16)
{
    const int gtid = bid * 256 + threadIdx.x;
    const int gstride = PBLOCKS * 256;

    const int total = S * B * RING * 16;   // 95232 uint4 stores
    for (int idx = gtid; idx < total; idx += gstride) {
        int chunk = idx & 15;
        int cellI = idx >> 4;
        int sb = cellI / RING;
        int c  = cellI % RING;
        int py, px;
        if (c < 4 * WP) {
            int rr = c / WP;
            py = (rr < 2) ? rr : rr + 32;
            px = c % WP;
        } else {
            int c2 = c - 4 * WP;
            py = 2 + (c2 >> 2);
            int e = c2 & 3;
            px = (e < 2) ? e : e + 88;
        }
        size_t base = ((size_t)sb * MP + py * WP + px) * C + chunk * 8;
        *(uint4*)&g_vproj[base] = make_uint4(0u, 0u, 0u, 0u);
    }

    unsigned occ = 0u;
    const int nvec = MASK_ELEMS / 16;
    for (int i = gtid; i < nvec; i += gstride) {
        uint4 v = __ldg(mask16 + i);
        unsigned w[4] = {v.x, v.y, v.z, v.w};
        #pragma unroll
        for (int wi = 0; wi < 4; wi++) {
            int base = (wi * 4) & 7;
            #pragma unroll
            for (int k = 0; k < 4; k++)
                if ((w[wi] >> (k * 8)) & 0xFFu) occ |= 1u << ((base + k) & 7);
        }
    }
    #pragma unroll
    for (int o = 16; o > 0; o >>= 1) occ |= __shfl_xor_sync(0xffffffffu, occ, o);
    if ((threadIdx.x & 31) == 0 && occ) atomicOr(&g_mask_occ, occ);
}

// ---------------------------------------------------------------------------
// vproj tile body: 64 rows, writes fp16 into the PADDED canvas.
// ---------------------------------------------------------------------------
__device__ __forceinline__ void vproj_tile(
    int bid,
    const float* __restrict__ value, const float* __restrict__ Wv,
    const float* __restrict__ bv, float (*svp)[64][2])
{
    const int t   = threadIdx.x;
    const int ro0 = bid * 64;
    const int tc  = t & 31;
    const int tm  = t >> 5;

    float2 acc[4][4];
    {
        float4 b4 = __ldg((const float4*)(bv + tc * 4));
        #pragma unroll
        for (int i = 0; i < 4; i++) {
            acc[i][0] = make_float2(b4.x, b4.x);
            acc[i][1] = make_float2(b4.y, b4.y);
            acc[i][2] = make_float2(b4.z, b4.z);
            acc[i][3] = make_float2(b4.w, b4.w);
        }
    }

    for (int kt = 0; kt < 2; kt++) {
        if (kt) __syncthreads();
        for (int idx = t; idx < 64 * 16; idx += 256) {
            int r  = idx >> 4;
            int k4 = (idx & 15) * 4;
            int ro = ro0 + r;
            int sb = ro / M, m = ro % M;
            int s  = sb / B, bb = sb % B;
            float4 v4 = *(const float4*)(value + ((size_t)((s * M + m) * B + bb) * C + kt * 64 + k4));
            svp[r >> 1][k4 + 0][r & 1] = v4.x;
            svp[r >> 1][k4 + 1][r & 1] = v4.y;
            svp[r >> 1][k4 + 2][r & 1] = v4.z;
            svp[r >> 1][k4 + 3][r & 1] = v4.w;
        }
        __syncthreads();

        const float* Wk = Wv + (size_t)(kt * 64) * C + tc * 4;
        #pragma unroll 2
        for (int k = 0; k < 64; k += 2) {
            float4 wa = __ldg((const float4*)(Wk + (size_t)k * C));
            float4 wb = __ldg((const float4*)(Wk + (size_t)(k + 1) * C));
            float2 wpa0 = make_float2(wa.x, wa.x), wpa1 = make_float2(wa.y, wa.y);
            float2 wpa2 = make_float2(wa.z, wa.z), wpa3 = make_float2(wa.w, wa.w);
            float2 wpb0 = make_float2(wb.x, wb.x), wpb1 = make_float2(wb.y, wb.y);
            float2 wpb2 = make_float2(wb.z, wb.z), wpb3 = make_float2(wb.w, wb.w);
            #pragma unroll
            for (int i = 0; i < 4; i++) {
                float4 a4 = *(const float4*)&svp[tm * 4 + i][k][0];
                float2 ak0 = make_float2(a4.x, a4.y);
                float2 ak1 = make_float2(a4.z, a4.w);
                ffma2(acc[i][0], ak0, wpa0); ffma2(acc[i][0], ak1, wpb0);
                ffma2(acc[i][1], ak0, wpa1); ffma2(acc[i][1], ak1, wpb1);
                ffma2(acc[i][2], ak0, wpa2); ffma2(acc[i][2], ak1, wpb2);
                ffma2(acc[i][3], ak0, wpa3); ffma2(acc[i][3], ak1, wpb3);
            }
        }
    }

    #pragma unroll
    for (int i = 0; i < 4; i++) {
        int r0 = ro0 + (tm * 4 + i) * 2;
        #pragma unroll
        for (int par = 0; par < 2; par++) {
            int ro = r0 + par;
            int sb = ro / M, m = ro % M;
            int y = m / Wf, x = m % Wf;
            size_t pm = (size_t)sb * MP + (y + 2) * WP + (x + 2);
            __half2 h01, h23;
            if (par == 0) {
                h01 = __floats2half2_rn(acc[i][0].x, acc[i][1].x);
                h23 = __floats2half2_rn(acc[i][2].x, acc[i][3].x);
            } else {
                h01 = __floats2half2_rn(acc[i][0].y, acc[i][1].y);
                h23 = __floats2half2_rn(acc[i][2].y, acc[i][3].y);
            }
            uint2 u; u.x = *(unsigned*)&h01; u.y = *(unsigned*)&h23;
            *(uint2*)&g_vproj[pm * C + tc * 4] = u;
        }
    }
}

// ---------------------------------------------------------------------------
// qproj tile body: 64 rows; offsets (64 cols) + logits (32 cols).
// ---------------------------------------------------------------------------
__device__ __forceinline__ void qproj_tile(
    int bid,
    const float* __restrict__ query, const float* __restrict__ qpos,
    const float* __restrict__ Woff, const float* __restrict__ boff,
    const float* __restrict__ Wa,   const float* __restrict__ ba,
    float (*svp)[64][2])
{
    const int t   = threadIdx.x;
    const int ro0 = bid * 64;
    const int tc  = t & 31;
    const int tm  = t >> 5;
    const int c   = tc * 4;
    const bool act = (tc < 24);

    float2 acc[4][4];
    if (act) {
        float4 b4;
        if (c < 64) b4 = *(const float4*)(boff + c);
        else        b4 = *(const float4*)(ba + (c - 64));
        #pragma unroll
        for (int i = 0; i < 4; i++) {
            acc[i][0] = make_float2(b4.x, b4.x);
            acc[i][1] = make_float2(b4.y, b4.y);
            acc[i][2] = make_float2(b4.z, b4.z);
            acc[i][3] = make_float2(b4.w, b4.w);
        }
    }

    for (int kt = 0; kt < 2; kt++) {
        if (kt) __syncthreads();
        for (int idx = t; idx < 64 * 16; idx += 256) {
            int r  = idx >> 4;
            int k4 = (idx & 15) * 4;
            int ro = min(ro0 + r, NROWS - 1);
            size_t off = (size_t)ro * C + kt * 64 + k4;
            float4 a = *(const float4*)(query + off);
            float4 p = *(const float4*)(qpos + off);
            svp[r >> 1][k4 + 0][r & 1] = a.x + p.x;
            svp[r >> 1][k4 + 1][r & 1] = a.y + p.y;
            svp[r >> 1][k4 + 2][r & 1] = a.z + p.z;
            svp[r >> 1][k4 + 3][r & 1] = a.w + p.w;
        }
        __syncthreads();

        if (act) {
            const float* Wk;
            int wstride;
            if (c < 64) { Wk = Woff + (size_t)(kt * 64) * 64 + c;        wstride = 64; }
            else        { Wk = Wa  + (size_t)(kt * 64) * 32 + (c - 64);  wstride = 32; }
            #pragma unroll 2
            for (int k = 0; k < 64; k += 2) {
                float4 wa4 = *(const float4*)(Wk + (size_t)k * wstride);
                float4 wb4 = *(const float4*)(Wk + (size_t)(k + 1) * wstride);
                float2 wpa0 = make_float2(wa4.x, wa4.x), wpa1 = make_float2(wa4.y, wa4.y);
                float2 wpa2 = make_float2(wa4.z, wa4.z), wpa3 = make_float2(wa4.w, wa4.w);
                float2 wpb0 = make_float2(wb4.x, wb4.x), wpb1 = make_float2(wb4.y, wb4.y);
                float2 wpb2 = make_float2(wb4.z, wb4.z), wpb3 = make_float2(wb4.w, wb4.w);
                #pragma unroll
                for (int i = 0; i < 4; i++) {
                    float4 a4 = *(const float4*)&svp[tm * 4 + i][k][0];
                    float2 ak0 = make_float2(a4.x, a4.y);
                    float2 ak1 = make_float2(a4.z, a4.w);
                    ffma2(acc[i][0], ak0, wpa0); ffma2(acc[i][0], ak1, wpb0);
                    ffma2(acc[i][1], ak0, wpa1); ffma2(acc[i][1], ak1, wpb1);
                    ffma2(acc[i][2], ak0, wpa2); ffma2(acc[i][2], ak1, wpb2);
                    ffma2(acc[i][3], ak0, wpa3); ffma2(acc[i][3], ak1, wpb3);
                }
            }
        }
    }

    if (act) {
        #pragma unroll
        for (int i = 0; i < 4; i++) {
            int r0 = ro0 + (tm * 4 + i) * 2;
            #pragma unroll
            for (int par = 0; par < 2; par++) {
                int row = r0 + par;
                if (row >= NROWS) continue;
                float4 v;
                if (par == 0) v = make_float4(acc[i][0].x, acc[i][1].x, acc[i][2].x, acc[i][3].x);
                else          v = make_float4(acc[i][0].y, acc[i][1].y, acc[i][2].y, acc[i][3].y);
                if (c < 64) *(float4*)(g_off    + (size_t)row * 64 + c)        = v;
                else        *(float4*)(g_logits + (size_t)row * 32 + (c - 64)) = v;
            }
        }
    }
}

// ---------------------------------------------------------------------------
// Kernel 1: FUSED prep + vproj + qproj.
// ---------------------------------------------------------------------------
__global__ void __launch_bounds__(256) k_proj(
    const float* __restrict__ value, const float* __restrict__ Wv,
    const float* __restrict__ bv,
    const float* __restrict__ query, const float* __restrict__ qpos,
    const float* __restrict__ Woff,  const float* __restrict__ boff,
    const float* __restrict__ Wa,    const float* __restrict__ ba,
    const uint4* __restrict__ mask16)
{
    __shared__ float svp[32][64][2];  // 16KB, shared by GEMM paths
    if (blockIdx.x < PBLOCKS)
        prep_body(blockIdx.x, mask16);
    else if (blockIdx.x < PBLOCKS + VBLOCKS)
        vproj_tile(blockIdx.x - PBLOCKS, value, Wv, bv, svp);
    else
        qproj_tile(blockIdx.x - PBLOCKS - VBLOCKS, query, qpos, Woff, boff, Wa, ba, svp);
}

// ---------------------------------------------------------------------------
// Kernel 2: bilinear sampling, TWO WARPS PER QUERY (cameras 0-2 / 3-5),
// 256-thread blocks = 4 queries, partial sums combined via shared memory.
// fp16 padded canvas, branchless clamp into zero ring.
// ---------------------------------------------------------------------------
__global__ void __launch_bounds__(256, 5) k_sample(
    const float* __restrict__ refpts,           // (S,B,N,D,2)
    const unsigned char* __restrict__ bev_mask) // (S,B,N,D), stride detected
{
    const unsigned FULL = 0xffffffffu;
    const int warp = threadIdx.x >> 5;   // 0..7
    const int lane = threadIdx.x & 31;
    const int qi   = warp >> 1;          // query within block 0..3
    const int half = warp & 1;           // camera half
    const int row  = blockIdx.x * 4 + qi; // b*N + n
    const int b    = row / N;
    const int n    = row % N;
    const int head = lane >> 3;
    const int sub  = lane & 7;

    __shared__ float  sm_ox[4][32];
    __shared__ float  sm_oy[4][32];
    __shared__ float  sm_wp[4][32];
    __shared__ float4 sm_acc[4][32];

    // per-warp preamble (both halves compute identically; half 0 publishes)
    float l = __ldg(g_logits + row * 32 + lane);   // lane = head*8 + p
    float mx = l;
    #pragma unroll
    for (int o = 4; o > 0; o >>= 1) mx = fmaxf(mx, __shfl_xor_sync(FULL, mx, o, 8));
    float e = expf(l - mx);
    float ssum = e;
    #pragma unroll
    for (int o = 4; o > 0; o >>= 1) ssum += __shfl_xor_sync(FULL, ssum, o, 8);
    float aw = e / ssum;

    float2 oxy = __ldg((const float2*)(g_off + row * 64) + lane);

    int sv = 0, hv = 0;
    unsigned occ = g_mask_occ;
    int st = (occ & 0x22u) ? 1 : ((occ & 0x1Cu) ? 4 : 8);
    if (lane < S) {
        int s = lane;
        long long e0 = ((long long)(s * B + 0) * N + n) * D;
        long long eb = ((long long)(s * B + b) * N + n) * D;
        #pragma unroll
        for (int d = 0; d < D; d++) {
            sv |= mask_nz(bev_mask, e0 + d, st);
            hv |= mask_nz(bev_mask, eb + d, st);
        }
    }
    unsigned selbits = __ballot_sync(FULL, (lane < S) && sv);
    unsigned hitbits = __ballot_sync(FULL, (lane < S) && hv);
    float inv_cnt = 1.0f / fmaxf((float)__popc(hitbits), 1.0f);

    if (half == 0) {
        // +1.5 = +2 (pad shift) - 0.5 (align_corners=False)
        sm_ox[qi][lane] = oxy.x + 1.5f;
        sm_oy[qi][lane] = oxy.y + 1.5f;
        sm_wp[qi][lane] = aw * inv_cnt;
    }
    __syncthreads();

    const float* oxp = &sm_ox[qi][head << 3];
    const float* oyp = &sm_oy[qi][head << 3];
    const float* wpp = &sm_wp[qi][head << 3];

    float4 acc = make_float4(0.f, 0.f, 0.f, 0.f);
    #pragma unroll
    for (int si = 0; si < 3; si++) {
        int s = half * 3 + si;
        if (!((selbits >> s) & 1u)) continue;  // warp-uniform
        const __half* vb = g_vproj + (size_t)((s * B + b) * MP) * C + head * 32 + sub * 4;
        const float4* rp4 = (const float4*)(refpts + (((size_t)(s * B + b) * N + n) * D) * 2);
        float4 r0 = __ldg(rp4), r1 = __ldg(rp4 + 1);
        float xb[D] = {r0.x * Wf, r0.z * Wf, r1.x * Wf, r1.z * Wf};
        float yb[D] = {r0.y * Hf, r0.w * Hf, r1.y * Hf, r1.w * Hf};

        #pragma unroll
        for (int p = 0; p < NP; p++) {
            int dz = p & 3;
            float x = xb[dz] + oxp[p];      // padded coords
            float y = yb[dz] + oyp[p];
            float xf = floorf(x), yf = floorf(y);
            float wx1 = x - xf, wy1 = y - yf;
            int px = min(max((int)xf, 0), WP - 2);
            int py = min(max((int)yf, 0), HP - 2);

            const uint2* base = (const uint2*)(vb + (py * WP + px) * C);
            uint2 u00 = __ldg(base);
            uint2 u01 = __ldg(base + (C / 4));
            uint2 u10 = __ldg(base + (WP * C / 4));
            uint2 u11 = __ldg(base + ((WP + 1) * C / 4));

            float wx0 = 1.0f - wx1, wy0 = 1.0f - wy1;
            __half2 hw00 = __float2half2_rn(wy0 * wx0);
            __half2 hw01 = __float2half2_rn(wy0 * wx1);
            __half2 hw10 = __float2half2_rn(wy1 * wx0);
            __half2 hw11 = __float2half2_rn(wy1 * wx1);

            __half2 sa = __hmul2(*(__half2*)&u00.x, hw00);
            sa = __hfma2(*(__half2*)&u01.x, hw01, sa);
            sa = __hfma2(*(__half2*)&u10.x, hw10, sa);
            sa = __hfma2(*(__half2*)&u11.x, hw11, sa);
            __half2 sb = __hmul2(*(__half2*)&u00.y, hw00);
            sb = __hfma2(*(__half2*)&u01.y, hw01, sb);
            sb = __hfma2(*(__half2*)&u10.y, hw10, sb);
            sb = __hfma2(*(__half2*)&u11.y, hw11, sb);

            float wgt = wpp[p];
            float2 fa = __half22float2(sa);
            float2 fb = __half22float2(sb);
            acc.x = fmaf(wgt, fa.x, acc.x);
            acc.y = fmaf(wgt, fa.y, acc.y);
            acc.z = fmaf(wgt, fb.x, acc.z);
            acc.w = fmaf(wgt, fb.y, acc.w);
        }
    }

    if (half == 1) sm_acc[qi][lane] = acc;
    __syncthreads();
    if (half == 0) {
        float4 o = sm_acc[qi][lane];
        acc.x += o.x; acc.y += o.y; acc.z += o.z; acc.w += o.w;
        *(float4*)(g_slots + (size_t)row * C + lane * 4) = acc;
    }
}

// ---------------------------------------------------------------------------
// Kernel 3: out = slots @ W_out + b_out + query. 32-row tiles (625 blocks).
// ---------------------------------------------------------------------------
__global__ void __launch_bounds__(256) k_out(
    const float* __restrict__ query,  // (B,N,C)
    const float* __restrict__ Wo,     // (C,C)
    const float* __restrict__ bo,     // (C,)
    float* __restrict__ out)          // (B,N,C)
{
    __shared__ float svp[16][64][2];  // 8KB
    const int t   = threadIdx.x;
    const int ro0 = blockIdx.x * 32;
    const int tc  = t & 31;
    const int tm  = t >> 5;

    float2 acc[2][4];
    {
        float4 b4 = __ldg((const float4*)(bo + tc * 4));
        #pragma unroll
        for (int i = 0; i < 2; i++) {
            acc[i][0] = make_float2(b4.x, b4.x);
            acc[i][1] = make_float2(b4.y, b4.y);
            acc[i][2] = make_float2(b4.z, b4.z);
            acc[i][3] = make_float2(b4.w, b4.w);
        }
    }

    for (int kt = 0; kt < 2; kt++) {
        if (kt) __syncthreads();
        for (int idx = t; idx < 32 * 16; idx += 256) {
            int r  = idx >> 4;
            int k4 = (idx & 15) * 4;
            int ro = min(ro0 + r, NROWS - 1);
            float4 v4 = *(const float4*)(g_slots + (size_t)ro * C + kt * 64 + k4);
            svp[r >> 1][k4 + 0][r & 1] = v4.x;
            svp[r >> 1][k4 + 1][r & 1] = v4.y;
            svp[r >> 1][k4 + 2][r & 1] = v4.z;
            svp[r >> 1][k4 + 3][r & 1] = v4.w;
        }
        __syncthreads();

        const float* Wk = Wo + (size_t)(kt * 64) * C + tc * 4;
        #pragma unroll 2
        for (int k = 0; k < 64; k += 2) {
            float4 wa = __ldg((const float4*)(Wk + (size_t)k * C));
            float4 wb = __ldg((const float4*)(Wk + (size_t)(k + 1) * C));
            float2 wpa0 = make_float2(wa.x, wa.x), wpa1 = make_float2(wa.y, wa.y);
            float2 wpa2 = make_float2(wa.z, wa.z), wpa3 = make_float2(wa.w, wa.w);
            float2 wpb0 = make_float2(wb.x, wb.x), wpb1 = make_float2(wb.y, wb.y);
            float2 wpb2 = make_float2(wb.z, wb.z), wpb3 = make_float2(wb.w, wb.w);
            #pragma unroll
            for (int i = 0; i < 2; i++) {
                float4 a4 = *(const float4*)&svp[tm * 2 + i][k][0];
                float2 ak0 = make_float2(a4.x, a4.y);
                float2 ak1 = make_float2(a4.z, a4.w);
                ffma2(acc[i][0], ak0, wpa0); ffma2(acc[i][0], ak1, wpb0);
                ffma2(acc[i][1], ak0, wpa1); ffma2(acc[i][1], ak1, wpb1);
                ffma2(acc[i][2], ak0, wpa2); ffma2(acc[i][2], ak1, wpb2);
                ffma2(acc[i][3], ak0, wpa3); ffma2(acc[i][3], ak1, wpb3);
            }
        }
    }

    #pragma unroll
    for (int i = 0; i < 2; i++) {
        int r0 = ro0 + (tm * 2 + i) * 2;
        #pragma unroll
        for (int par = 0; par < 2; par++) {
            int row = r0 + par;
            if (row >= NROWS) continue;
            size_t off = (size_t)row * C + tc * 4;
            float4 q4 = *(const float4*)(query + off);
            float4 v;
            if (par == 0) v = make_float4(acc[i][0].x + q4.x, acc[i][1].x + q4.y,
                                          acc[i][2].x + q4.z, acc[i][3].x + q4.w);
            else          v = make_float4(acc[i][0].y + q4.x, acc[i][1].y + q4.y,
                                          acc[i][2].y + q4.z, acc[i][3].y + q4.w);
            *(float4*)(out + off) = v;
        }
    }
}

// ---------------------------------------------------------------------------
// Launch. Input order: query, key, value, query_pos, reference_points_cam,
// bev_mask, spatial_shapes, W_value, b_value, W_offsets, b_offsets,
// W_attn, b_attn, W_out, b_out.
// ---------------------------------------------------------------------------
extern "C" void kernel_launch(void* const* d_in, const int* in_sizes, int n_in,
                              void* d_out, int out_size)
{
    const float* query = (const float*)d_in[0];
    // d_in[1] = key: unused by the reference math
    const float* value = (const float*)d_in[2];
    const float* qpos  = (const float*)d_in[3];
    const float* refp  = (const float*)d_in[4];
    const unsigned char* mask = (const unsigned char*)d_in[5];
    // d_in[6] = spatial_shapes (static, hardcoded H=32, W=88)
    const float* Wv   = (const float*)d_in[7];
    const float* bv   = (const float*)d_in[8];
    const float* Woff = (const float*)d_in[9];
    const float* boff = (const float*)d_in[10];
    const float* Wa   = (const float*)d_in[11];
    const float* ba   = (const float*)d_in[12];
    const float* Wo   = (const float*)d_in[13];
    const float* bo   = (const float*)d_in[14];
    float* out = (float*)d_out;

    k_proj  <<<PBLOCKS + VBLOCKS + QBLOCKS, 256>>>(value, Wv, bv, query, qpos,
                                                   Woff, boff, Wa, ba,
                                                   (const uint4*)mask);
    k_sample<<<NROWS / 4, 256>>>(refp, mask);
    k_out   <<<OBLOCKS, 256>>>(query, Wo, bo, out);
}

// round 16
// speedup vs baseline: 1.0649x; 1.0649x over previous
#include <cuda_runtime.h>
#include <cuda_fp16.h>

// Problem constants (static per reference)
constexpr int B  = 2;
constexpr int S  = 6;
constexpr int N  = 10000;
constexpr int C  = 128;
constexpr int D  = 4;
constexpr int NH = 4;     // heads
constexpr int NP = 8;     // points
constexpr int Hf = 32;
constexpr int Wf = 88;
constexpr int M  = Hf * Wf;        // 2816
constexpr int WP = Wf + 4;         // 92  (2-px pad each side)
constexpr int HP = Hf + 4;         // 36
constexpr int MP = HP * WP;        // 3312 padded pixels
constexpr int RING = MP - M;       // 496 pad cells per (s,b)
constexpr int MASK_ELEMS = S * B * N * D;  // 480000
constexpr int NROWS = B * N;               // 20000
constexpr int VBLOCKS = (S * B * M) / 64;  // 528 vproj tiles
constexpr int QBLOCKS = (NROWS + 63) / 64; // 313 qproj tiles
constexpr int OBLOCKS = (NROWS + 31) / 32; // 625 out tiles

// Scratch (device globals; no allocation allowed)
__device__ __half   g_vproj [S * B * MP * C];       // padded (s,b,py,px,c) fp16
__device__ float    g_off   [B * N * NH * NP * 2];  // offsets (pixel units)
__device__ float    g_logits[B * N * NH * NP];      // attn logits
__device__ float    g_slots [B * N * C];            // masked-mean slots
__device__ unsigned g_mask_occ;                     // byte-position occupancy

// packed fp32x2 FMA (Blackwell): d = a*b + d elementwise
__device__ __forceinline__ void ffma2(float2& d, float2 a, float2 b) {
    asm("fma.rn.f32x2 %0, %1, %2, %0;"
        : "+l"(reinterpret_cast<unsigned long long&>(d))
        : "l"(reinterpret_cast<unsigned long long&>(a)),
          "l"(reinterpret_cast<unsigned long long&>(b)));
}

// ---------------------------------------------------------------------------
// Kernel 0: fused mask-dtype probe + pad-ring zerofill (separate launch —
// fusing it into k_proj measured WORSE in R15: long prep blocks stretched
// the GEMM grid).
// ---------------------------------------------------------------------------
__global__ void k_prep(const uint4* __restrict__ mask16)
{
    const int gtid = blockIdx.x * blockDim.x + threadIdx.x;
    const int gstride = gridDim.x * blockDim.x;

    const int total = S * B * RING * 16;   // 95232 uint4 stores
    for (int idx = gtid; idx < total; idx += gstride) {
        int chunk = idx & 15;
        int cellI = idx >> 4;
        int sb = cellI / RING;
        int c  = cellI % RING;
        int py, px;
        if (c < 4 * WP) {                   // rows 0,1,34,35 (full width)
            int rr = c / WP;
            py = (rr < 2) ? rr : rr + 32;
            px = c % WP;
        } else {
            int c2 = c - 4 * WP;
            py = 2 + (c2 >> 2);
            int e = c2 & 3;
            px = (e < 2) ? e : e + 88;
        }
        size_t base = ((size_t)sb * MP + py * WP + px) * C + chunk * 8;
        *(uint4*)&g_vproj[base] = make_uint4(0u, 0u, 0u, 0u);
    }

    unsigned occ = 0u;
    const int nvec = MASK_ELEMS / 16;
    for (int i = gtid; i < nvec; i += gstride) {
        uint4 v = __ldg(mask16 + i);
        unsigned w[4] = {v.x, v.y, v.z, v.w};
        #pragma unroll
        for (int wi = 0; wi < 4; wi++) {
            int base = (wi * 4) & 7;
            #pragma unroll
            for (int k = 0; k < 4; k++)
                if ((w[wi] >> (k * 8)) & 0xFFu) occ |= 1u << ((base + k) & 7);
        }
    }
    #pragma unroll
    for (int o = 16; o > 0; o >>= 1) occ |= __shfl_xor_sync(0xffffffffu, occ, o);
    if ((threadIdx.x & 31) == 0 && occ) atomicOr(&g_mask_occ, occ);
}

__device__ __forceinline__ int mask_nz(const unsigned char* __restrict__ mask,
                                       long long elem, int st)
{
    const unsigned char* p = mask + elem * st;
    int v = 0;
    for (int j = 0; j < st; j++) v |= p[j];
    return v != 0;
}

// ---------------------------------------------------------------------------
// vproj tile body: 64 rows, writes fp16 into the PADDED canvas.
// ---------------------------------------------------------------------------
__device__ __forceinline__ void vproj_tile(
    int bid,
    const float* __restrict__ value, const float* __restrict__ Wv,
    const float* __restrict__ bv, float (*svp)[64][2])
{
    const int t   = threadIdx.x;
    const int ro0 = bid * 64;
    const int tc  = t & 31;
    const int tm  = t >> 5;

    float2 acc[4][4];
    {
        float4 b4 = __ldg((const float4*)(bv + tc * 4));
        #pragma unroll
        for (int i = 0; i < 4; i++) {
            acc[i][0] = make_float2(b4.x, b4.x);
            acc[i][1] = make_float2(b4.y, b4.y);
            acc[i][2] = make_float2(b4.z, b4.z);
            acc[i][3] = make_float2(b4.w, b4.w);
        }
    }

    for (int kt = 0; kt < 2; kt++) {
        if (kt) __syncthreads();
        for (int idx = t; idx < 64 * 16; idx += 256) {
            int r  = idx >> 4;
            int k4 = (idx & 15) * 4;
            int ro = ro0 + r;
            int sb = ro / M, m = ro % M;
            int s  = sb / B, bb = sb % B;
            float4 v4 = *(const float4*)(value + ((size_t)((s * M + m) * B + bb) * C + kt * 64 + k4));
            svp[r >> 1][k4 + 0][r & 1] = v4.x;
            svp[r >> 1][k4 + 1][r & 1] = v4.y;
            svp[r >> 1][k4 + 2][r & 1] = v4.z;
            svp[r >> 1][k4 + 3][r & 1] = v4.w;
        }
        __syncthreads();

        const float* Wk = Wv + (size_t)(kt * 64) * C + tc * 4;
        #pragma unroll 2
        for (int k = 0; k < 64; k += 2) {
            float4 wa = __ldg((const float4*)(Wk + (size_t)k * C));
            float4 wb = __ldg((const float4*)(Wk + (size_t)(k + 1) * C));
            float2 wpa0 = make_float2(wa.x, wa.x), wpa1 = make_float2(wa.y, wa.y);
            float2 wpa2 = make_float2(wa.z, wa.z), wpa3 = make_float2(wa.w, wa.w);
            float2 wpb0 = make_float2(wb.x, wb.x), wpb1 = make_float2(wb.y, wb.y);
            float2 wpb2 = make_float2(wb.z, wb.z), wpb3 = make_float2(wb.w, wb.w);
            #pragma unroll
            for (int i = 0; i < 4; i++) {
                float4 a4 = *(const float4*)&svp[tm * 4 + i][k][0];
                float2 ak0 = make_float2(a4.x, a4.y);
                float2 ak1 = make_float2(a4.z, a4.w);
                ffma2(acc[i][0], ak0, wpa0); ffma2(acc[i][0], ak1, wpb0);
                ffma2(acc[i][1], ak0, wpa1); ffma2(acc[i][1], ak1, wpb1);
                ffma2(acc[i][2], ak0, wpa2); ffma2(acc[i][2], ak1, wpb2);
                ffma2(acc[i][3], ak0, wpa3); ffma2(acc[i][3], ak1, wpb3);
            }
        }
    }

    #pragma unroll
    for (int i = 0; i < 4; i++) {
        int r0 = ro0 + (tm * 4 + i) * 2;
        #pragma unroll
        for (int par = 0; par < 2; par++) {
            int ro = r0 + par;
            int sb = ro / M, m = ro % M;
            int y = m / Wf, x = m % Wf;
            size_t pm = (size_t)sb * MP + (y + 2) * WP + (x + 2);
            __half2 h01, h23;
            if (par == 0) {
                h01 = __floats2half2_rn(acc[i][0].x, acc[i][1].x);
                h23 = __floats2half2_rn(acc[i][2].x, acc[i][3].x);
            } else {
                h01 = __floats2half2_rn(acc[i][0].y, acc[i][1].y);
                h23 = __floats2half2_rn(acc[i][2].y, acc[i][3].y);
            }
            uint2 u; u.x = *(unsigned*)&h01; u.y = *(unsigned*)&h23;
            *(uint2*)&g_vproj[pm * C + tc * 4] = u;
        }
    }
}

// ---------------------------------------------------------------------------
// qproj tile body: 64 rows; offsets (64 cols) + logits (32 cols).
// ---------------------------------------------------------------------------
__device__ __forceinline__ void qproj_tile(
    int bid,
    const float* __restrict__ query, const float* __restrict__ qpos,
    const float* __restrict__ Woff, const float* __restrict__ boff,
    const float* __restrict__ Wa,   const float* __restrict__ ba,
    float (*svp)[64][2])
{
    const int t   = threadIdx.x;
    const int ro0 = bid * 64;
    const int tc  = t & 31;
    const int tm  = t >> 5;
    const int c   = tc * 4;
    const bool act = (tc < 24);

    float2 acc[4][4];
    if (act) {
        float4 b4;
        if (c < 64) b4 = *(const float4*)(boff + c);
        else        b4 = *(const float4*)(ba + (c - 64));
        #pragma unroll
        for (int i = 0; i < 4; i++) {
            acc[i][0] = make_float2(b4.x, b4.x);
            acc[i][1] = make_float2(b4.y, b4.y);
            acc[i][2] = make_float2(b4.z, b4.z);
            acc[i][3] = make_float2(b4.w, b4.w);
        }
    }

    for (int kt = 0; kt < 2; kt++) {
        if (kt) __syncthreads();
        for (int idx = t; idx < 64 * 16; idx += 256) {
            int r  = idx >> 4;
            int k4 = (idx & 15) * 4;
            int ro = min(ro0 + r, NROWS - 1);
            size_t off = (size_t)ro * C + kt * 64 + k4;
            float4 a = *(const float4*)(query + off);
            float4 p = *(const float4*)(qpos + off);
            svp[r >> 1][k4 + 0][r & 1] = a.x + p.x;
            svp[r >> 1][k4 + 1][r & 1] = a.y + p.y;
            svp[r >> 1][k4 + 2][r & 1] = a.z + p.z;
            svp[r >> 1][k4 + 3][r & 1] = a.w + p.w;
        }
        __syncthreads();

        if (act) {
            const float* Wk;
            int wstride;
            if (c < 64) { Wk = Woff + (size_t)(kt * 64) * 64 + c;        wstride = 64; }
            else        { Wk = Wa  + (size_t)(kt * 64) * 32 + (c - 64);  wstride = 32; }
            #pragma unroll 2
            for (int k = 0; k < 64; k += 2) {
                float4 wa4 = *(const float4*)(Wk + (size_t)k * wstride);
                float4 wb4 = *(const float4*)(Wk + (size_t)(k + 1) * wstride);
                float2 wpa0 = make_float2(wa4.x, wa4.x), wpa1 = make_float2(wa4.y, wa4.y);
                float2 wpa2 = make_float2(wa4.z, wa4.z), wpa3 = make_float2(wa4.w, wa4.w);
                float2 wpb0 = make_float2(wb4.x, wb4.x), wpb1 = make_float2(wb4.y, wb4.y);
                float2 wpb2 = make_float2(wb4.z, wb4.z), wpb3 = make_float2(wb4.w, wb4.w);
                #pragma unroll
                for (int i = 0; i < 4; i++) {
                    float4 a4 = *(const float4*)&svp[tm * 4 + i][k][0];
                    float2 ak0 = make_float2(a4.x, a4.y);
                    float2 ak1 = make_float2(a4.z, a4.w);
                    ffma2(acc[i][0], ak0, wpa0); ffma2(acc[i][0], ak1, wpb0);
                    ffma2(acc[i][1], ak0, wpa1); ffma2(acc[i][1], ak1, wpb1);
                    ffma2(acc[i][2], ak0, wpa2); ffma2(acc[i][2], ak1, wpb2);
                    ffma2(acc[i][3], ak0, wpa3); ffma2(acc[i][3], ak1, wpb3);
                }
            }
        }
    }

    if (act) {
        #pragma unroll
        for (int i = 0; i < 4; i++) {
            int r0 = ro0 + (tm * 4 + i) * 2;
            #pragma unroll
            for (int par = 0; par < 2; par++) {
                int row = r0 + par;
                if (row >= NROWS) continue;
                float4 v;
                if (par == 0) v = make_float4(acc[i][0].x, acc[i][1].x, acc[i][2].x, acc[i][3].x);
                else          v = make_float4(acc[i][0].y, acc[i][1].y, acc[i][2].y, acc[i][3].y);
                if (c < 64) *(float4*)(g_off    + (size_t)row * 64 + c)        = v;
                else        *(float4*)(g_logits + (size_t)row * 32 + (c - 64)) = v;
            }
        }
    }
}

// ---------------------------------------------------------------------------
// Kernel 1: FUSED vproj + qproj. min 4 blocks/SM (<=64 regs) to lift
// occupancy 24 -> 32 warps/SM (R15 profile: fma 49.7% @ occ 34.1%).
// ---------------------------------------------------------------------------
__global__ void __launch_bounds__(256, 4) k_proj(
    const float* __restrict__ value, const float* __restrict__ Wv,
    const float* __restrict__ bv,
    const float* __restrict__ query, const float* __restrict__ qpos,
    const float* __restrict__ Woff,  const float* __restrict__ boff,
    const float* __restrict__ Wa,    const float* __restrict__ ba)
{
    __shared__ float svp[32][64][2];  // 16KB, shared by both paths
    if (blockIdx.x < VBLOCKS)
        vproj_tile(blockIdx.x, value, Wv, bv, svp);
    else
        qproj_tile(blockIdx.x - VBLOCKS, query, qpos, Woff, boff, Wa, ba, svp);
}

// ---------------------------------------------------------------------------
// Kernel 2: bilinear sampling, ONE WARP PER QUERY (R14 proven form),
// fp16 padded canvas, branchless clamp into zero ring.
// ---------------------------------------------------------------------------
__global__ void __launch_bounds__(128, 10) k_sample(
    const float* __restrict__ refpts,           // (S,B,N,D,2)
    const unsigned char* __restrict__ bev_mask) // (S,B,N,D), stride detected
{
    const unsigned FULL = 0xffffffffu;
    const int warp = threadIdx.x >> 5;
    const int lane = threadIdx.x & 31;
    const int row  = blockIdx.x * 4 + warp;  // b*N + n
    const int b    = row / N;
    const int n    = row % N;
    const int head = lane >> 3;
    const int sub  = lane & 7;

    __shared__ float sm_ox[4][32];
    __shared__ float sm_oy[4][32];
    __shared__ float sm_wp[4][32];

    float l = __ldg(g_logits + row * 32 + lane);   // lane = head*8 + p
    float mx = l;
    #pragma unroll
    for (int o = 4; o > 0; o >>= 1) mx = fmaxf(mx, __shfl_xor_sync(FULL, mx, o, 8));
    float e = expf(l - mx);
    float ssum = e;
    #pragma unroll
    for (int o = 4; o > 0; o >>= 1) ssum += __shfl_xor_sync(FULL, ssum, o, 8);
    float aw = e / ssum;

    float2 oxy = __ldg((const float2*)(g_off + row * 64) + lane);

    int sv = 0, hv = 0;
    unsigned occ = g_mask_occ;
    int st = (occ & 0x22u) ? 1 : ((occ & 0x1Cu) ? 4 : 8);
    if (lane < S) {
        int s = lane;
        long long e0 = ((long long)(s * B + 0) * N + n) * D;
        long long eb = ((long long)(s * B + b) * N + n) * D;
        #pragma unroll
        for (int d = 0; d < D; d++) {
            sv |= mask_nz(bev_mask, e0 + d, st);
            hv |= mask_nz(bev_mask, eb + d, st);
        }
    }
    unsigned selbits = __ballot_sync(FULL, (lane < S) && sv);
    unsigned hitbits = __ballot_sync(FULL, (lane < S) && hv);
    float inv_cnt = 1.0f / fmaxf((float)__popc(hitbits), 1.0f);

    // +1.5 = +2 (pad shift) - 0.5 (align_corners=False)
    sm_ox[warp][lane] = oxy.x + 1.5f;
    sm_oy[warp][lane] = oxy.y + 1.5f;
    sm_wp[warp][lane] = aw * inv_cnt;
    __syncwarp();

    const float* oxp = &sm_ox[warp][head << 3];
    const float* oyp = &sm_oy[warp][head << 3];
    const float* wpp = &sm_wp[warp][head << 3];

    float4 acc = make_float4(0.f, 0.f, 0.f, 0.f);
    #pragma unroll
    for (int s = 0; s < S; s++) {
        if (!((selbits >> s) & 1u)) continue;  // warp-uniform
        const __half* vb = g_vproj + (size_t)((s * B + b) * MP) * C + head * 32 + sub * 4;
        const float4* rp4 = (const float4*)(refpts + (((size_t)(s * B + b) * N + n) * D) * 2);
        float4 r0 = __ldg(rp4), r1 = __ldg(rp4 + 1);
        float xb[D] = {r0.x * Wf, r0.z * Wf, r1.x * Wf, r1.z * Wf};
        float yb[D] = {r0.y * Hf, r0.w * Hf, r1.y * Hf, r1.w * Hf};

        #pragma unroll
        for (int p = 0; p < NP; p++) {
            int dz = p & 3;
            float x = xb[dz] + oxp[p];      // padded coords
            float y = yb[dz] + oyp[p];
            float xf = floorf(x), yf = floorf(y);
            float wx1 = x - xf, wy1 = y - yf;
            int px = min(max((int)xf, 0), WP - 2);
            int py = min(max((int)yf, 0), HP - 2);

            const uint2* base = (const uint2*)(vb + (py * WP + px) * C);
            uint2 u00 = __ldg(base);
            uint2 u01 = __ldg(base + (C / 4));
            uint2 u10 = __ldg(base + (WP * C / 4));
            uint2 u11 = __ldg(base + ((WP + 1) * C / 4));

            float wx0 = 1.0f - wx1, wy0 = 1.0f - wy1;
            __half2 hw00 = __float2half2_rn(wy0 * wx0);
            __half2 hw01 = __float2half2_rn(wy0 * wx1);
            __half2 hw10 = __float2half2_rn(wy1 * wx0);
            __half2 hw11 = __float2half2_rn(wy1 * wx1);

            __half2 sa = __hmul2(*(__half2*)&u00.x, hw00);
            sa = __hfma2(*(__half2*)&u01.x, hw01, sa);
            sa = __hfma2(*(__half2*)&u10.x, hw10, sa);
            sa = __hfma2(*(__half2*)&u11.x, hw11, sa);
            __half2 sb = __hmul2(*(__half2*)&u00.y, hw00);
            sb = __hfma2(*(__half2*)&u01.y, hw01, sb);
            sb = __hfma2(*(__half2*)&u10.y, hw10, sb);
            sb = __hfma2(*(__half2*)&u11.y, hw11, sb);

            float wgt = wpp[p];
            float2 fa = __half22float2(sa);
            float2 fb = __half22float2(sb);
            acc.x = fmaf(wgt, fa.x, acc.x);
            acc.y = fmaf(wgt, fa.y, acc.y);
            acc.z = fmaf(wgt, fb.x, acc.z);
            acc.w = fmaf(wgt, fb.y, acc.w);
        }
    }
    *(float4*)(g_slots + (size_t)row * C + lane * 4) = acc;
}

// ---------------------------------------------------------------------------
// Kernel 3: out = slots @ W_out + b_out + query. 32-row tiles (625 blocks).
// ---------------------------------------------------------------------------
__global__ void __launch_bounds__(256) k_out(
    const float* __restrict__ query,  // (B,N,C)
    const float* __restrict__ Wo,     // (C,C)
    const float* __restrict__ bo,     // (C,)
    float* __restrict__ out)          // (B,N,C)
{
    __shared__ float svp[16][64][2];  // 8KB
    const int t   = threadIdx.x;
    const int ro0 = blockIdx.x * 32;
    const int tc  = t & 31;
    const int tm  = t >> 5;

    float2 acc[2][4];
    {
        float4 b4 = __ldg((const float4*)(bo + tc * 4));
        #pragma unroll
        for (int i = 0; i < 2; i++) {
            acc[i][0] = make_float2(b4.x, b4.x);
            acc[i][1] = make_float2(b4.y, b4.y);
            acc[i][2] = make_float2(b4.z, b4.z);
            acc[i][3] = make_float2(b4.w, b4.w);
        }
    }

    for (int kt = 0; kt < 2; kt++) {
        if (kt) __syncthreads();
        for (int idx = t; idx < 32 * 16; idx += 256) {
            int r  = idx >> 4;
            int k4 = (idx & 15) * 4;
            int ro = min(ro0 + r, NROWS - 1);
            float4 v4 = *(const float4*)(g_slots + (size_t)ro * C + kt * 64 + k4);
            svp[r >> 1][k4 + 0][r & 1] = v4.x;
            svp[r >> 1][k4 + 1][r & 1] = v4.y;
            svp[r >> 1][k4 + 2][r & 1] = v4.z;
            svp[r >> 1][k4 + 3][r & 1] = v4.w;
        }
        __syncthreads();

        const float* Wk = Wo + (size_t)(kt * 64) * C + tc * 4;
        #pragma unroll 2
        for (int k = 0; k < 64; k += 2) {
            float4 wa = __ldg((const float4*)(Wk + (size_t)k * C));
            float4 wb = __ldg((const float4*)(Wk + (size_t)(k + 1) * C));
            float2 wpa0 = make_float2(wa.x, wa.x), wpa1 = make_float2(wa.y, wa.y);
            float2 wpa2 = make_float2(wa.z, wa.z), wpa3 = make_float2(wa.w, wa.w);
            float2 wpb0 = make_float2(wb.x, wb.x), wpb1 = make_float2(wb.y, wb.y);
            float2 wpb2 = make_float2(wb.z, wb.z), wpb3 = make_float2(wb.w, wb.w);
            #pragma unroll
            for (int i = 0; i < 2; i++) {
                float4 a4 = *(const float4*)&svp[tm * 2 + i][k][0];
                float2 ak0 = make_float2(a4.x, a4.y);
                float2 ak1 = make_float2(a4.z, a4.w);
                ffma2(acc[i][0], ak0, wpa0); ffma2(acc[i][0], ak1, wpb0);
                ffma2(acc[i][1], ak0, wpa1); ffma2(acc[i][1], ak1, wpb1);
                ffma2(acc[i][2], ak0, wpa2); ffma2(acc[i][2], ak1, wpb2);
                ffma2(acc[i][3], ak0, wpa3); ffma2(acc[i][3], ak1, wpb3);
            }
        }
    }

    #pragma unroll
    for (int i = 0; i < 2; i++) {
        int r0 = ro0 + (tm * 2 + i) * 2;
        #pragma unroll
        for (int par = 0; par < 2; par++) {
            int row = r0 + par;
            if (row >= NROWS) continue;
            size_t off = (size_t)row * C + tc * 4;
            float4 q4 = *(const float4*)(query + off);
            float4 v;
            if (par == 0) v = make_float4(acc[i][0].x + q4.x, acc[i][1].x + q4.y,
                                          acc[i][2].x + q4.z, acc[i][3].x + q4.w);
            else          v = make_float4(acc[i][0].y + q4.x, acc[i][1].y + q4.y,
                                          acc[i][2].y + q4.z, acc[i][3].y + q4.w);
            *(float4*)(out + off) = v;
        }
    }
}

// ---------------------------------------------------------------------------
// Launch. Input order: query, key, value, query_pos, reference_points_cam,
// bev_mask, spatial_shapes, W_value, b_value, W_offsets, b_offsets,
// W_attn, b_attn, W_out, b_out.
// ---------------------------------------------------------------------------
extern "C" void kernel_launch(void* const* d_in, const int* in_sizes, int n_in,
                              void* d_out, int out_size)
{
    const float* query = (const float*)d_in[0];
    // d_in[1] = key: unused by the reference math
    const float* value = (const float*)d_in[2];
    const float* qpos  = (const float*)d_in[3];
    const float* refp  = (const float*)d_in[4];
    const unsigned char* mask = (const unsigned char*)d_in[5];
    // d_in[6] = spatial_shapes (static, hardcoded H=32, W=88)
    const float* Wv   = (const float*)d_in[7];
    const float* bv   = (const float*)d_in[8];
    const float* Woff = (const float*)d_in[9];
    const float* boff = (const float*)d_in[10];
    const float* Wa   = (const float*)d_in[11];
    const float* ba   = (const float*)d_in[12];
    const float* Wo   = (const float*)d_in[13];
    const float* bo   = (const float*)d_in[14];
    float* out = (float*)d_out;

    k_prep  <<<148, 256>>>((const uint4*)mask);
    k_proj  <<<VBLOCKS + QBLOCKS, 256>>>(value, Wv, bv, query, qpos, Woff, boff, Wa, ba);
    k_sample<<<NROWS / 4, 128>>>(refp, mask);
    k_out   <<<OBLOCKS, 256>>>(query, Wo, bo, out);
}